// round 10
// baseline (speedup 1.0000x reference)
#include <cuda_runtime.h>
#include <math.h>
#include <stdint.h>
#include <mma.h>
#include <cuda_fp16.h>

using namespace nvcuda;

#define BB 8
#define CC 256
#define SS 16384
#define EPSV 1e-5f
#define KSPLIT 16

// ---------------- scratch ----------------
__device__ float g_Gp[(size_t)KSPLIT*BB*CC*CC];
__device__ float g_G [BB*CC*CC];
__device__ float g_P [BB*CC*CC];
__device__ float g_L [BB*CC*CC];
__device__ float g_M [BB*CC*CC];
__device__ float g_Aq[CC*CC];
__device__ float g_Ak[CC*CC];
__device__ float g_AvT[CC*CC];
__device__ float g_bq[CC];
__device__ float g_bk[CC];
__device__ float g_bv[CC];
__device__ float g_s [BB*CC];
__device__ float g_u [BB*CC];
__device__ float g_w [BB*CC];
__device__ float g_cv[BB*CC];

// ---------------- fp16 two-term split ----------------
__device__ __forceinline__ void split2h(float v, __half& h, __half& l) {
    h = __float2half_rn(v);
    l = __float2half_rn(v - __half2float(h));
}

// ---------------- reductions ----------------
__device__ __forceinline__ float blockReduceSum(float v) {
    __shared__ float sh[8];
    int lane = threadIdx.x & 31, wid = threadIdx.x >> 5;
#pragma unroll
    for (int o = 16; o; o >>= 1) v += __shfl_xor_sync(0xffffffffu, v, o);
    if (lane == 0) sh[wid] = v;
    __syncthreads();
    float r = 0.f;
#pragma unroll
    for (int i = 0; i < 8; i++) r += sh[i];
    __syncthreads();
    return r;
}
__device__ __forceinline__ float blockReduceMax(float v) {
    __shared__ float sh[8];
    int lane = threadIdx.x & 31, wid = threadIdx.x >> 5;
#pragma unroll
    for (int o = 16; o; o >>= 1) v = fmaxf(v, __shfl_xor_sync(0xffffffffu, v, o));
    if (lane == 0) sh[wid] = v;
    __syncthreads();
    float r = -3.402823466e38f;
#pragma unroll
    for (int i = 0; i < 8; i++) r = fmaxf(r, sh[i]);
    __syncthreads();
    return r;
}

// ---------------- prep ----------------
__global__ void prep_kernel(
    const float* __restrict__ Wk, const float* __restrict__ kg, const float* __restrict__ kb,
    const float* __restrict__ km, const float* __restrict__ kvv,
    const float* __restrict__ Wq, const float* __restrict__ qg, const float* __restrict__ qb,
    const float* __restrict__ qm, const float* __restrict__ qv,
    const float* __restrict__ Wv, const float* __restrict__ vg, const float* __restrict__ vb,
    const float* __restrict__ vm, const float* __restrict__ vv)
{
    int o = blockIdx.x, m = blockIdx.y, i = threadIdx.x;
    const float *W, *ga, *be, *me, *va;
    if (m == 0)      { W = Wq; ga = qg; be = qb; me = qm; va = qv; }
    else if (m == 1) { W = Wk; ga = kg; be = kb; me = km; va = kvv; }
    else             { W = Wv; ga = vg; be = vb; me = vm; va = vv; }
    float inv = ga[o] / sqrtf(va[o] + EPSV);
    float a = inv * W[o*CC + i];
    if (m == 0)      { g_Aq[o*CC + i] = a;  if (i == 0) g_bq[o] = be[o] - me[o]*inv; }
    else if (m == 1) { g_Ak[o*CC + i] = a;  if (i == 0) g_bk[o] = be[o] - me[o]*inv; }
    else             { g_AvT[i*CC + o] = a; if (i == 0) g_bv[o] = be[o] - me[o]*inv; }
}

// ---------------- rowsum ----------------
__global__ void rowsum_kernel(const float* __restrict__ x) {
    int c = blockIdx.x, n = blockIdx.y, t = threadIdx.x;
    const float4* xr = (const float4*)(x + ((size_t)n*CC + c)*SS);
    float acc = 0.f;
    for (int i = t; i < SS/4; i += 256) {
        float4 v = xr[i];
        acc += (v.x + v.y) + (v.z + v.w);
    }
    float tot = blockReduceSum(acc);
    if (t == 0) g_s[n*CC + c] = tot;
}

// ---------------- gram via 3xFP16 WMMA, 64x64 warp tiles, 2-stage pipeline ----------------
#define GLDH 40
#define GSTR (4*128*GLDH)                 /* halves per stage */
#define GRAM_SMEM (2*GSTR*2)              /* 81920 B */
__global__ void __launch_bounds__(128, 2) gram_wmma_kernel(const float* __restrict__ x) {
    extern __shared__ char smraw[];
    __half* S = (__half*)smraw;
    const int bx = blockIdx.x;                 // 0:(0,0) 1:(0,1) 2:(1,1)
    const int bi = (bx == 2) ? 1 : 0;
    const int bj = (bx == 0) ? 0 : 1;
    const bool diag = (bi == bj);

    const int tid = threadIdx.x, w = tid >> 5;
    const int wm = w >> 1, wn = w & 1;         // 2x2 warps -> 64x64 tiles
    const int zk = blockIdx.y, n = blockIdx.z;
    const int s0 = zk * (SS / KSPLIT);

    const float* xa = x + ((size_t)n*CC + bi*128 + tid)*SS + s0;
    const float* xb = x + ((size_t)n*CC + bj*128 + tid)*SS + s0;

    wmma::fragment<wmma::accumulator, 16, 16, 16, float> acc[4][4];
#pragma unroll
    for (int i = 0; i < 4; i++)
#pragma unroll
        for (int j = 0; j < 4; j++) wmma::fill_fragment(acc[i][j], 0.0f);

    const int NT = SS/KSPLIT/32;   // 32 iterations

    auto stage = [&](int st, int t) {
        __half* Ah = S + st*GSTR;
        __half* Al = Ah + 128*GLDH;
        __half* Bh = Al + 128*GLDH;
        __half* Bl = Bh + 128*GLDH;
#pragma unroll
        for (int q = 0; q < 8; q++) {
            float4 v = *(const float4*)(xa + t*32 + q*4);
            int o = tid*GLDH + q*4;
            split2h(v.x, Ah[o+0], Al[o+0]); split2h(v.y, Ah[o+1], Al[o+1]);
            split2h(v.z, Ah[o+2], Al[o+2]); split2h(v.w, Ah[o+3], Al[o+3]);
        }
        if (!diag) {
#pragma unroll
            for (int q = 0; q < 8; q++) {
                float4 v = *(const float4*)(xb + t*32 + q*4);
                int o = tid*GLDH + q*4;
                split2h(v.x, Bh[o+0], Bl[o+0]); split2h(v.y, Bh[o+1], Bl[o+1]);
                split2h(v.z, Bh[o+2], Bl[o+2]); split2h(v.w, Bh[o+3], Bl[o+3]);
            }
        }
    };

    auto domma = [&](int st) {
        __half* Ah = S + st*GSTR;
        __half* Al = Ah + 128*GLDH;
        __half* Bh = diag ? Ah : (Al + 128*GLDH);
        __half* Bl = diag ? Al : (Al + 2*128*GLDH);
#pragma unroll
        for (int ks = 0; ks < 2; ks++) {
            wmma::fragment<wmma::matrix_b, 16, 16, 16, __half, wmma::col_major> bh[4], bl[4];
#pragma unroll
            for (int j = 0; j < 4; j++) {
                wmma::load_matrix_sync(bh[j], &Bh[(wn*64 + j*16)*GLDH + ks*16], GLDH);
                wmma::load_matrix_sync(bl[j], &Bl[(wn*64 + j*16)*GLDH + ks*16], GLDH);
            }
#pragma unroll
            for (int i = 0; i < 4; i++) {
                wmma::fragment<wmma::matrix_a, 16, 16, 16, __half, wmma::row_major> ah, al;
                wmma::load_matrix_sync(ah, &Ah[(wm*64 + i*16)*GLDH + ks*16], GLDH);
                wmma::load_matrix_sync(al, &Al[(wm*64 + i*16)*GLDH + ks*16], GLDH);
#pragma unroll
                for (int j = 0; j < 4; j++) {
                    wmma::mma_sync(acc[i][j], ah, bl[j], acc[i][j]);
                    wmma::mma_sync(acc[i][j], al, bh[j], acc[i][j]);
                    wmma::mma_sync(acc[i][j], ah, bh[j], acc[i][j]);
                }
            }
        }
    };

    stage(0, 0);
    __syncthreads();
    int st = 0;
    for (int t = 0; t < NT; t++) {
        if (t + 1 < NT) stage(st ^ 1, t + 1);
        domma(st);
        __syncthreads();
        st ^= 1;
    }

    float* gp = g_Gp + ((size_t)zk*BB + n)*CC*CC;
#pragma unroll
    for (int i = 0; i < 4; i++)
#pragma unroll
        for (int j = 0; j < 4; j++) {
            wmma::store_matrix_sync(
                gp + (size_t)(bi*128 + wm*64 + i*16)*CC + bj*128 + wn*64 + j*16,
                acc[i][j], CC, wmma::mem_row_major);
            if (!diag)
                wmma::store_matrix_sync(
                    gp + (size_t)(bj*128 + wn*64 + j*16)*CC + bi*128 + wm*64 + i*16,
                    acc[i][j], CC, wmma::mem_col_major);
        }
}

// ---------------- reduce gram partials ----------------
__global__ void reduceG_kernel() {
    size_t i = (size_t)blockIdx.x*256 + threadIdx.x;
    float s = 0.f;
#pragma unroll
    for (int z = 0; z < KSPLIT; z++) s += g_Gp[(size_t)z*(BB*CC*CC) + i];
    g_G[i] = s;
}

// ---------------- middle chain: 256^3 NT GEMM (SIMT fp32) ----------------
__global__ void __launch_bounds__(256) gemm256_nt_kernel(int mode) {
    __shared__ float As[16*64];
    __shared__ float Bs[16*64];
    int bj = blockIdx.x, bi = blockIdx.y, n = blockIdx.z;
    int tid = threadIdx.x, tx = tid & 15, ty = tid >> 4;
    int lrow = tid >> 2, lc4 = tid & 3;

    const float* A; const float* Bm; float* Out;
    if (mode == 0)      { A = g_Aq;                  Bm = g_G + (size_t)n*CC*CC; Out = g_P + (size_t)n*CC*CC; }
    else if (mode == 1) { A = g_P + (size_t)n*CC*CC; Bm = g_Ak;                  Out = g_L + (size_t)n*CC*CC; }
    else                { A = g_L + (size_t)n*CC*CC; Bm = g_AvT;                 Out = g_M + (size_t)n*CC*CC; }

    const float* ap = A  + (size_t)(bi*64 + lrow)*CC + lc4*4;
    const float* bp = Bm + (size_t)(bj*64 + lrow)*CC + lc4*4;

    float acc[4][4] = {};
    float4 a = *(const float4*)ap;
    float4 b = *(const float4*)bp;

    for (int kc = 0; kc < CC; kc += 16) {
        As[(lc4*4+0)*64 + lrow] = a.x;  As[(lc4*4+1)*64 + lrow] = a.y;
        As[(lc4*4+2)*64 + lrow] = a.z;  As[(lc4*4+3)*64 + lrow] = a.w;
        Bs[(lc4*4+0)*64 + lrow] = b.x;  Bs[(lc4*4+1)*64 + lrow] = b.y;
        Bs[(lc4*4+2)*64 + lrow] = b.z;  Bs[(lc4*4+3)*64 + lrow] = b.w;
        __syncthreads();
        int kn = (kc + 16 < CC) ? kc + 16 : kc;
        a = *(const float4*)(ap + kn);
        b = *(const float4*)(bp + kn);
#pragma unroll
        for (int kk = 0; kk < 16; kk++) {
            float4 av = *(const float4*)&As[kk*64 + ty*4];
            float4 bv = *(const float4*)&Bs[kk*64 + tx*4];
            acc[0][0] += av.x*bv.x; acc[0][1] += av.x*bv.y; acc[0][2] += av.x*bv.z; acc[0][3] += av.x*bv.w;
            acc[1][0] += av.y*bv.x; acc[1][1] += av.y*bv.y; acc[1][2] += av.y*bv.z; acc[1][3] += av.y*bv.w;
            acc[2][0] += av.z*bv.x; acc[2][1] += av.z*bv.y; acc[2][2] += av.z*bv.z; acc[2][3] += av.z*bv.w;
            acc[3][0] += av.w*bv.x; acc[3][1] += av.w*bv.y; acc[3][2] += av.w*bv.z; acc[3][3] += av.w*bv.w;
        }
        __syncthreads();
    }

    int row = bi*64 + ty*4, col = bj*64 + tx*4;
    if (mode == 1) {
#pragma unroll
        for (int u = 0; u < 4; u++) {
            float uu = g_u[n*CC + row + u], bb = g_bq[row + u];
#pragma unroll
            for (int v = 0; v < 4; v++) {
                float bk = g_bk[col + v];
                acc[u][v] += uu*bk + bb*(g_w[n*CC + col + v] + (float)SS*bk);
            }
        }
    } else if (mode == 2) {
#pragma unroll
        for (int u = 0; u < 4; u++)
#pragma unroll
            for (int v = 0; v < 4; v++)
                if (row + u == col + v) acc[u][v] += 1.0f;
    }

    float* out = Out + (size_t)row*CC + col;
#pragma unroll
    for (int u = 0; u < 4; u++)
        *(float4*)(out + (size_t)u*CC) = make_float4(acc[u][0], acc[u][1], acc[u][2], acc[u][3]);
}

// ---------------- matvecs (modes 0,1 in one launch via blockIdx.z) ----------------
__global__ void matvec01_kernel() {
    int r = blockIdx.x, n = blockIdx.y, m = blockIdx.z, t = threadIdx.x;
    const float* Arow = (m == 0) ? (g_Aq + (size_t)r*CC) : (g_Ak + (size_t)r*CC);
    float* out = (m == 0) ? (g_u + n*CC + r) : (g_w + n*CC + r);
    float p = Arow[t] * g_s[n*CC + t];
    float tot = blockReduceSum(p);
    if (t == 0) *out = tot;
}

// ---------------- softmax + cv = attn @ bv fused ----------------
__global__ void softmax_kernel() {
    int r = blockIdx.x, n = blockIdx.y, t = threadIdx.x;
    float* row = g_L + ((size_t)n*CC + r)*CC;
    float v = row[t];
    float m = blockReduceMax(v);
    float e = expf(v - m);
    float ss = blockReduceSum(e);
    float a = e / ss;
    row[t] = a;
    float cv = blockReduceSum(a * g_bv[t]);
    if (t == 0) g_cv[n*CC + r] = cv;
}

// ---------------- out = (M+I) @ X + c via 3xFP16 WMMA, 64x64 warp tiles ----------------
#define OLDAH 40            /* A staging stride (halves) */
#define OLDBH 136           /* B staging stride (halves) */
#define OLDC  132           /* C epilogue stride (floats) */
#define OSTR (2*128*OLDAH + 2*32*OLDBH)      /* halves per stage = 18944 */
#define OUT_SMEM (2*OSTR*2 > 128*OLDC*4 ? 2*OSTR*2 : 128*OLDC*4)  /* 75776 */
__global__ void __launch_bounds__(128, 2) out_wmma_kernel(const float* __restrict__ x,
                                                          float* __restrict__ out) {
    extern __shared__ char smraw[];
    __half* S  = (__half*)smraw;
    float*  Cs = (float*)smraw;             // epilogue reuse

    const int tid = threadIdx.x, w = tid >> 5;
    const int wm = w >> 1, wn = w & 1;      // 2x2 warps -> 64x64 tiles
    const int bs = blockIdx.x, bc = blockIdx.y, n = blockIdx.z;
    const int s0 = bs*128, c0 = bc*128;

    const float* Mfb = g_M + (size_t)n*CC*CC;
    const float* Xb  = x + (size_t)n*CC*SS;

    wmma::fragment<wmma::accumulator, 16, 16, 16, float> acc[4][4];
#pragma unroll
    for (int i = 0; i < 4; i++)
#pragma unroll
        for (int j = 0; j < 4; j++) wmma::fill_fragment(acc[i][j], 0.0f);

    auto stage = [&](int st, int kb) {
        __half* Ahs = S + st*OSTR;
        __half* Als = Ahs + 128*OLDAH;
        __half* Bhs = Als + 128*OLDAH;
        __half* Bls = Bhs + 32*OLDBH;
#pragma unroll
        for (int q = 0; q < 8; q++) {
            float4 v = *(const float4*)(Mfb + (size_t)(c0 + tid)*CC + kb + q*4);
            int o = tid*OLDAH + q*4;
            split2h(v.x, Ahs[o+0], Als[o+0]); split2h(v.y, Ahs[o+1], Als[o+1]);
            split2h(v.z, Ahs[o+2], Als[o+2]); split2h(v.w, Ahs[o+3], Als[o+3]);
        }
#pragma unroll
        for (int i = 0; i < 8; i++) {
            int idx = i*128 + tid;
            int r = idx >> 5, c4 = idx & 31;
            float4 v = *(const float4*)(Xb + (size_t)(kb + r)*SS + s0 + c4*4);
            int o = r*OLDBH + c4*4;
            split2h(v.x, Bhs[o+0], Bls[o+0]); split2h(v.y, Bhs[o+1], Bls[o+1]);
            split2h(v.z, Bhs[o+2], Bls[o+2]); split2h(v.w, Bhs[o+3], Bls[o+3]);
        }
    };

    auto domma = [&](int st) {
        __half* Ahs = S + st*OSTR;
        __half* Als = Ahs + 128*OLDAH;
        __half* Bhs = Als + 128*OLDAH;
        __half* Bls = Bhs + 32*OLDBH;
#pragma unroll
        for (int ks = 0; ks < 2; ks++) {
            wmma::fragment<wmma::matrix_b, 16, 16, 16, __half, wmma::row_major> bh[4], bl[4];
#pragma unroll
            for (int j = 0; j < 4; j++) {
                wmma::load_matrix_sync(bh[j], &Bhs[(ks*16)*OLDBH + wn*64 + j*16], OLDBH);
                wmma::load_matrix_sync(bl[j], &Bls[(ks*16)*OLDBH + wn*64 + j*16], OLDBH);
            }
#pragma unroll
            for (int i = 0; i < 4; i++) {
                wmma::fragment<wmma::matrix_a, 16, 16, 16, __half, wmma::row_major> ah, al;
                wmma::load_matrix_sync(ah, &Ahs[(wm*64 + i*16)*OLDAH + ks*16], OLDAH);
                wmma::load_matrix_sync(al, &Als[(wm*64 + i*16)*OLDAH + ks*16], OLDAH);
#pragma unroll
                for (int j = 0; j < 4; j++) {
                    wmma::mma_sync(acc[i][j], ah, bl[j], acc[i][j]);
                    wmma::mma_sync(acc[i][j], al, bh[j], acc[i][j]);
                    wmma::mma_sync(acc[i][j], ah, bh[j], acc[i][j]);
                }
            }
        }
    };

    stage(0, 0);
    __syncthreads();
    int st = 0;
    for (int kb = 0; kb < CC; kb += 32) {
        if (kb + 32 < CC) stage(st ^ 1, kb + 32);
        domma(st);
        __syncthreads();
        st ^= 1;
    }

#pragma unroll
    for (int i = 0; i < 4; i++)
#pragma unroll
        for (int j = 0; j < 4; j++)
            wmma::store_matrix_sync(&Cs[(wm*64 + i*16)*OLDC + wn*64 + j*16],
                                    acc[i][j], OLDC, wmma::mem_row_major);
    __syncthreads();

    float cv = g_cv[n*CC + c0 + tid];
    float* op = out + ((size_t)n*CC + c0 + tid)*SS + s0;
#pragma unroll
    for (int q = 0; q < 32; q++) {
        float4 v = *(float4*)&Cs[tid*OLDC + q*4];
        v.x += cv; v.y += cv; v.z += cv; v.w += cv;
        *(float4*)(op + q*4) = v;
    }
}

// ---------------- launcher ----------------
extern "C" void kernel_launch(void* const* d_in, const int* in_sizes, int n_in,
                              void* d_out, int out_size) {
    const float* x   = (const float*)d_in[0];
    const float* Wk  = (const float*)d_in[1];
    const float* kg  = (const float*)d_in[2];
    const float* kb  = (const float*)d_in[3];
    const float* km  = (const float*)d_in[4];
    const float* kv  = (const float*)d_in[5];
    const float* Wq  = (const float*)d_in[6];
    const float* qg  = (const float*)d_in[7];
    const float* qb  = (const float*)d_in[8];
    const float* qm  = (const float*)d_in[9];
    const float* qv  = (const float*)d_in[10];
    const float* Wv  = (const float*)d_in[11];
    const float* vg  = (const float*)d_in[12];
    const float* vb  = (const float*)d_in[13];
    const float* vm  = (const float*)d_in[14];
    const float* vv  = (const float*)d_in[15];
    float* out = (float*)d_out;

    cudaFuncSetAttribute(gram_wmma_kernel, cudaFuncAttributeMaxDynamicSharedMemorySize, GRAM_SMEM);
    cudaFuncSetAttribute(out_wmma_kernel,  cudaFuncAttributeMaxDynamicSharedMemorySize, OUT_SMEM);

    prep_kernel<<<dim3(CC, 3), CC>>>(Wk, kg, kb, km, kv, Wq, qg, qb, qm, qv, Wv, vg, vb, vm, vv);
    rowsum_kernel<<<dim3(CC, BB), 256>>>(x);
    matvec01_kernel<<<dim3(CC, BB, 2), 256>>>();                  // u, w
    gram_wmma_kernel<<<dim3(3, KSPLIT, BB), 128, GRAM_SMEM>>>(x); // <- profiled slot
    reduceG_kernel<<<BB*CC*CC/256, 256>>>();
    gemm256_nt_kernel<<<dim3(4, 4, BB), 256>>>(0);   // P = Aq @ G
    gemm256_nt_kernel<<<dim3(4, 4, BB), 256>>>(1);   // L = P @ Ak^T + rank-1
    softmax_kernel<<<dim3(CC, BB), 256>>>();         // attn + cv fused
    gemm256_nt_kernel<<<dim3(4, 4, BB), 256>>>(2);   // M = attn @ Av + I
    out_wmma_kernel<<<dim3(SS/128, CC/128, BB), 128, OUT_SMEM>>>(x, out);
}